// round 1
// baseline (speedup 1.0000x reference)
#include <cuda_runtime.h>
#include <cstdint>

#define HDIM 4096
#define EXP  64
#define BM   128
#define BK   32

// per-expert claim threshold (k-th largest logit of that expert's column)
__device__ float g_thresh[EXP];

// ---------------------------------------------------------------------------
// Kernel 1: logits[N,64] = x[N,4096] @ W[4096,64], exact fp32 accumulate.
// Packed f32x2 FMAs: acc lanes = adjacent token rows, b broadcast per column.
// ---------------------------------------------------------------------------
__global__ __launch_bounds__(256) void gemm_kernel(const float* __restrict__ x,
                                                   const float* __restrict__ W,
                                                   float* __restrict__ logits) {
    __shared__ float xs[BK][BM + 2];   // k-major x tile (row pairs contiguous)
    __shared__ float ws[BK][EXP];

    const int tid  = threadIdx.x;
    const int row0 = blockIdx.x * BM;
    const int cg   = tid & 15;   // cols cg*4 .. cg*4+3
    const int rg   = tid >> 4;   // rows rg*8 .. rg*8+7

    unsigned long long acc[4][4];  // [col j][row-pair ip]; lanes = (row 2ip, row 2ip+1)
#pragma unroll
    for (int j = 0; j < 4; ++j)
#pragma unroll
        for (int ip = 0; ip < 4; ++ip) acc[j][ip] = 0ULL;

    const int lr = tid >> 3;          // load row within 32-row pass
    const int lc = (tid & 7) * 4;     // load col (float4)

    for (int k0 = 0; k0 < HDIM; k0 += BK) {
        // stage x tile [BM x BK] -> xs[k][row]
#pragma unroll
        for (int p = 0; p < 4; ++p) {
            int r = lr + p * 32;
            float4 v = *(const float4*)(x + (size_t)(row0 + r) * HDIM + k0 + lc);
            xs[lc + 0][r] = v.x; xs[lc + 1][r] = v.y;
            xs[lc + 2][r] = v.z; xs[lc + 3][r] = v.w;
        }
        // stage W tile [BK x 64]
#pragma unroll
        for (int p = 0; p < 2; ++p) {
            int idx = tid + p * 256;
            int r = idx >> 4;
            int c = (idx & 15) * 4;
            *(float4*)&ws[r][c] = *(const float4*)(W + (size_t)(k0 + r) * EXP + c);
        }
        __syncthreads();

#pragma unroll
        for (int k = 0; k < BK; ++k) {
            float4 bv = *(const float4*)&ws[k][cg * 4];
            unsigned long long b2[4];
            asm("mov.b64 %0, {%1, %1};" : "=l"(b2[0]) : "r"(__float_as_uint(bv.x)));
            asm("mov.b64 %0, {%1, %1};" : "=l"(b2[1]) : "r"(__float_as_uint(bv.y)));
            asm("mov.b64 %0, {%1, %1};" : "=l"(b2[2]) : "r"(__float_as_uint(bv.z)));
            asm("mov.b64 %0, {%1, %1};" : "=l"(b2[3]) : "r"(__float_as_uint(bv.w)));
            unsigned long long a2[4];
#pragma unroll
            for (int ip = 0; ip < 4; ++ip)
                a2[ip] = *(const unsigned long long*)&xs[k][rg * 8 + ip * 2];
#pragma unroll
            for (int j = 0; j < 4; ++j)
#pragma unroll
                for (int ip = 0; ip < 4; ++ip)
                    asm("fma.rn.f32x2 %0, %1, %2, %0;"
                        : "+l"(acc[j][ip]) : "l"(a2[ip]), "l"(b2[j]));
        }
        __syncthreads();
    }

    // writeback: 8 rows x 4 cols per thread, float4 per row
#pragma unroll
    for (int ip = 0; ip < 4; ++ip) {
        float lo[4], hi[4];
#pragma unroll
        for (int j = 0; j < 4; ++j) {
            lo[j] = __uint_as_float((unsigned)(acc[j][ip] & 0xFFFFFFFFULL));
            hi[j] = __uint_as_float((unsigned)(acc[j][ip] >> 32));
        }
        int r = row0 + rg * 8 + ip * 2;
        *(float4*)(logits + (size_t)r * EXP + cg * 4) =
            make_float4(lo[0], lo[1], lo[2], lo[3]);
        *(float4*)(logits + (size_t)(r + 1) * EXP + cg * 4) =
            make_float4(hi[0], hi[1], hi[2], hi[3]);
    }
}

// ---------------------------------------------------------------------------
// Kernel 2: per-expert k-th largest logit via 4-pass (8-bit) radix select.
// One CTA per expert. Keys: monotone float->uint transform.
// ---------------------------------------------------------------------------
__global__ __launch_bounds__(256) void select_kernel(const float* __restrict__ logits,
                                                     int N, int k) {
    __shared__ unsigned hist[256];
    __shared__ unsigned s_prefix, s_remk;
    const int e   = blockIdx.x;
    const int tid = threadIdx.x;

    if (tid == 0) { s_prefix = 0u; s_remk = (unsigned)k; }
    unsigned pmask = 0u;
    __syncthreads();

    for (int byte = 3; byte >= 0; --byte) {
        hist[tid] = 0u;
        __syncthreads();
        const unsigned prefix = s_prefix;
        const int shift = byte * 8;
        for (int i = tid; i < N; i += 256) {
            unsigned u = __float_as_uint(logits[(size_t)i * EXP + e]);
            u ^= (u & 0x80000000u) ? 0xFFFFFFFFu : 0x80000000u;  // sortable
            if ((u & pmask) == prefix)
                atomicAdd(&hist[(u >> shift) & 255u], 1u);
        }
        __syncthreads();
        if (tid == 0) {
            unsigned remk = s_remk, cum = 0;
            int b = 255;
            for (; b > 0; --b) {
                unsigned h = hist[b];
                if (cum + h >= remk) break;
                cum += h;
            }
            s_prefix = prefix | ((unsigned)b << shift);
            s_remk   = remk - cum;
        }
        pmask |= 0xFFu << shift;
        __syncthreads();
    }

    if (tid == 0) {
        unsigned key  = s_prefix;
        unsigned bits = (key & 0x80000000u) ? (key ^ 0x80000000u) : ~key;
        g_thresh[e] = __uint_as_float(bits);
    }
}

// ---------------------------------------------------------------------------
// Kernel 3: conflict resolution + fallback argmax. One warp per token.
// claimed(e) iff logit >= thresh_e; winner = max score, tie -> smallest e.
// ---------------------------------------------------------------------------
__global__ __launch_bounds__(256) void assign_kernel(const float* __restrict__ logits,
                                                     float* __restrict__ out_w,
                                                     float* __restrict__ out_i,
                                                     int N) {
    const int gwarp = (int)((blockIdx.x * (size_t)blockDim.x + threadIdx.x) >> 5);
    const int lane  = threadIdx.x & 31;
    if (gwarp >= N) return;

    const float NEG_INF = __int_as_float(0xff800000);
    float2 v = *(const float2*)(logits + (size_t)gwarp * EXP + lane * 2);
    float t0 = g_thresh[lane * 2];
    float t1 = g_thresh[lane * 2 + 1];

    float cs = NEG_INF; int ci = 127;                  // claimed best
    if (v.x >= t0)             { cs = v.x; ci = lane * 2; }
    if (v.y >= t1 && v.y > cs) { cs = v.y; ci = lane * 2 + 1; }

    float fs = v.x; int fi = lane * 2;                 // fallback argmax
    if (v.y > fs) { fs = v.y; fi = lane * 2 + 1; }

#pragma unroll
    for (int off = 16; off; off >>= 1) {
        float os = __shfl_xor_sync(0xFFFFFFFFu, cs, off);
        int   oi = __shfl_xor_sync(0xFFFFFFFFu, ci, off);
        if (os > cs || (os == cs && oi < ci)) { cs = os; ci = oi; }
        float ofs = __shfl_xor_sync(0xFFFFFFFFu, fs, off);
        int   ofi = __shfl_xor_sync(0xFFFFFFFFu, fi, off);
        if (ofs > fs || (ofs == fs && ofi < fi)) { fs = ofs; fi = ofi; }
    }

    if (lane == 0) {
        float w; int e;
        if (ci < EXP) { w = cs; e = ci; }   // assigned
        else          { w = fs; e = fi; }   // fallback
        out_w[gwarp] = w;
        out_i[gwarp] = (float)e;
    }
}

// ---------------------------------------------------------------------------
// Output layout (reference returns tuple in this order, flattened):
//   [0, N)        routing_weights
//   [N, 2N)       expert_indices (as float)
//   [2N, 2N+N*E)  logits
// ---------------------------------------------------------------------------
extern "C" void kernel_launch(void* const* d_in, const int* in_sizes, int n_in,
                              void* d_out, int out_size) {
    const float* x = (const float*)d_in[0];
    const float* W = (const float*)d_in[1];
    const int N = in_sizes[0] / HDIM;   // 32768

    float* out    = (float*)d_out;
    float* out_w  = out;
    float* out_i  = out + N;
    float* logits = out + 2 * (size_t)N;

    int k = N / EXP;
    if (k < 1) k = 1;
    if (k > N) k = N;

    gemm_kernel<<<N / BM, 256>>>(x, W, logits);
    select_kernel<<<EXP, 256>>>(logits, N, k);
    assign_kernel<<<(int)(((size_t)N * 32 + 255) / 256), 256>>>(logits, out_w, out_i, N);
}